// round 17
// baseline (speedup 1.0000x reference)
#include <cuda_runtime.h>
#include <cuda_bf16.h>

#define B_    16
#define LL_   256
#define LP_   1024
#define HID_  128
#define H_    8
#define HD_   1024

// ---------------- scratch ----------------
__device__ float g_l12[B_ * LL_ * 2 * HD_];             // [b][l][l1|l2]
__device__ float g_p1[B_ * LP_ * HD_];
__device__ float g_p2t[B_ * HD_ * LP_];                 // [b][h*128+d][p]
__device__ __nv_bfloat16 g_att[(size_t)B_ * H_ * LL_ * LP_];  // exp weights (bf16)
__device__ float g_lig3x[B_ * LL_ * 1152];              // [4096][lig3(1024)|ligr(128)]
__device__ float g_prot3x[(size_t)B_ * LP_ * 1152];     // [16384][prot3(1024)|protr(128)]
__device__ float g_ligr[B_ * LL_ * HID_];
__device__ float g_protr[B_ * LP_ * HID_];
__device__ float g_l2s[B_ * LL_ * HD_];
__device__ float g_epart[B_ * H_ * LL_ * 8];
__device__ float g_rs[B_ * H_ * LL_];
__device__ float g_w[851968];
__device__ float g_b12[2048];
__device__ float g_w11r[131072];                        // rounded original W11 [1024][128]
__device__ float g_w21r[131072];                        // rounded original W21 [1024][128]
__device__ float g_bcl[128 * 1152];                     // combined lig out-weight [n][k]
__device__ float g_bcp[128 * 1152];                     // combined prot out-weight [n][k]
__device__ float g_bias2[256];                          // folded biases: lig[0:128], prot[128:256]

#define OW_L1  0
#define OW_L2  131072
#define OW_P1  262144
#define OW_P2  393216
#define OW_11  524288
#define OW_21  655360
#define OW_12  786432
#define OW_22  819200

// ---------------- helpers ----------------
__device__ __forceinline__ unsigned tf32_of(float f) {
    unsigned r;
    asm("cvt.rna.tf32.f32 %0, %1;" : "=r"(r) : "f"(f));
    return r;
}
__device__ __forceinline__ float tf32f(float f) { return __uint_as_float(tf32_of(f)); }

__device__ __forceinline__ void mma_tf32(float c[4], const unsigned a[4], const unsigned b[2]) {
    asm volatile(
        "mma.sync.aligned.m16n8k8.row.col.f32.tf32.tf32.f32 "
        "{%0,%1,%2,%3}, {%4,%5,%6,%7}, {%8,%9}, {%0,%1,%2,%3};"
        : "+f"(c[0]), "+f"(c[1]), "+f"(c[2]), "+f"(c[3])
        : "r"(a[0]), "r"(a[1]), "r"(a[2]), "r"(a[3]), "r"(b[0]), "r"(b[1]));
}

__device__ __forceinline__ void cp16(float* sm, const void* gm) {
    unsigned a = (unsigned)__cvta_generic_to_shared(sm);
    asm volatile("cp.async.cg.shared.global [%0], [%1], 16;" :: "r"(a), "l"(gm));
}
#define CP_COMMIT() asm volatile("cp.async.commit_group;" ::: "memory")
#define CP_WAIT2()  asm volatile("cp.async.wait_group 2;" ::: "memory")
#define CP_WAIT1()  asm volatile("cp.async.wait_group 1;" ::: "memory")

// shared epilogue. BIASM: 0 none, 1 bias[col], 2 bias[row], 3 row-scale by bias[row]
template<int BIASM, bool RELU, bool ROUND>
__device__ __forceinline__ void epilogue(float acc[4][4][4], float* C, const float* bias,
                                         int bm, int bn, int ldc, int mw, int nw, int g, int tg)
{
#pragma unroll
    for (int mt = 0; mt < 4; mt++) {
#pragma unroll
        for (int nt = 0; nt < 4; nt++) {
            int row = bm + mw * 64 + mt * 16 + g;
            int col = bn + nw * 32 + nt * 8 + 2 * tg;
            float x0 = acc[mt][nt][0], x1 = acc[mt][nt][1];
            float x2 = acc[mt][nt][2], x3 = acc[mt][nt][3];
            if (BIASM == 1) {
                float b0 = bias[col], b1 = bias[col + 1];
                x0 += b0; x1 += b1; x2 += b0; x3 += b1;
            } else if (BIASM == 2) {
                float br = bias[row], br8 = bias[row + 8];
                x0 += br; x1 += br; x2 += br8; x3 += br8;
            } else if (BIASM == 3) {
                float br = bias[row], br8 = bias[row + 8];
                x0 *= br; x1 *= br; x2 *= br8; x3 *= br8;
            }
            if (RELU) {
                x0 = fmaxf(x0, 0.f); x1 = fmaxf(x1, 0.f);
                x2 = fmaxf(x2, 0.f); x3 = fmaxf(x3, 0.f);
            }
            if (ROUND) { x0 = tf32f(x0); x1 = tf32f(x1); x2 = tf32f(x2); x3 = tf32f(x3); }
            *(float2*)(C + (size_t)row * ldc + col) = make_float2(x0, x1);
            *(float2*)(C + (size_t)(row + 8) * ldc + col) = make_float2(x2, x3);
        }
    }
}

// ================= cp-body: A [m][k] fp32, B [n][k] fp32, 3-stage cp.async =================
template<int BIASM, bool RELU, bool ROUND>
__device__ __forceinline__ void cp_body(const float* __restrict__ A, const float* __restrict__ B,
                                        const float* __restrict__ bias, float* __restrict__ C,
                                        int K, int lda, int ldb, int ldc,
                                        int bm, int bn, float* sm)
{
    const int tid  = threadIdx.x;
    const int lane = tid & 31, warp = tid >> 5;
    const int mw = warp & 1, nw = warp >> 1;
    const int g = lane >> 2, tg = lane & 3;

    const int r0 = tid >> 2,  kc = (tid & 3) << 2;
    const int r1 = r0 + 64;
    const float* gA0 = A + (size_t)(bm + r0) * lda + kc;
    const float* gA1 = A + (size_t)(bm + r1) * lda + kc;
    const float* gB0 = B + (size_t)(bn + r0) * ldb + kc;
    const float* gB1 = B + (size_t)(bn + r1) * ldb + kc;
    const int so = r0 * 16 + kc;
    const int s1 = r1 * 16 + kc;

    float acc[4][4][4];
#pragma unroll
    for (int i = 0; i < 4; i++)
#pragma unroll
        for (int j = 0; j < 4; j++)
#pragma unroll
            for (int r = 0; r < 4; r++) acc[i][j][r] = 0.f;

    const int nk = K >> 4;

    auto issue = [&](int t) {
        float* base = sm + (t % 3) * 4096;
        const size_t ko = (size_t)t << 4;
        cp16(base + so,        gA0 + ko);
        cp16(base + s1,        gA1 + ko);
        cp16(base + 2048 + so, gB0 + ko);
        cp16(base + 2048 + s1, gB1 + ko);
    };

    issue(0); CP_COMMIT();
    if (nk > 1) issue(1);
    CP_COMMIT();

    for (int t = 0; t < nk; t++) {
        if (t + 2 < nk) issue(t + 2);
        CP_COMMIT();
        CP_WAIT2();
        __syncthreads();

        const float* As = sm + (t % 3) * 4096;
        const float* Bs = As + 2048;

        float4 bf[4];
#pragma unroll
        for (int nt = 0; nt < 4; nt++)
            bf[nt] = *(const float4*)(Bs + (nw * 32 + nt * 8 + g) * 16 + 4 * tg);

#pragma unroll
        for (int mt = 0; mt < 4; mt++) {
            const int m0 = mw * 64 + mt * 16;
            float4 a0 = *(const float4*)(As + (m0 + g) * 16 + 4 * tg);
            float4 a1 = *(const float4*)(As + (m0 + g + 8) * 16 + 4 * tg);
            unsigned af0[4] = {__float_as_uint(a0.x), __float_as_uint(a1.x),
                               __float_as_uint(a0.y), __float_as_uint(a1.y)};
            unsigned af1[4] = {__float_as_uint(a0.z), __float_as_uint(a1.z),
                               __float_as_uint(a0.w), __float_as_uint(a1.w)};
#pragma unroll
            for (int nt = 0; nt < 4; nt++) {
                unsigned b0[2] = {__float_as_uint(bf[nt].x), __float_as_uint(bf[nt].y)};
                mma_tf32(acc[mt][nt], af0, b0);
            }
#pragma unroll
            for (int nt = 0; nt < 4; nt++) {
                unsigned b1[2] = {__float_as_uint(bf[nt].z), __float_as_uint(bf[nt].w)};
                mma_tf32(acc[mt][nt], af1, b1);
            }
        }
        __syncthreads();
    }

    epilogue<BIASM, RELU, ROUND>(acc, C, bias, bm, bn, ldc, mw, nw, g, tg);
}

// ========== cp_bf_body: A [m][k] BF16, B [n][k] fp32, 3-stage cp.async ==========
template<int BIASM, bool RELU, bool ROUND>
__device__ __forceinline__ void cp_bf_body(const __nv_bfloat16* __restrict__ A,
                                           const float* __restrict__ B,
                                           const float* __restrict__ bias, float* __restrict__ C,
                                           int K, int lda, int ldb, int ldc,
                                           int bm, int bn, float* sm)
{
    const int tid  = threadIdx.x;
    const int lane = tid & 31, warp = tid >> 5;
    const int mw = warp & 1, nw = warp >> 1;
    const int g = lane >> 2, tg = lane & 3;

    const int SF = 3072;

    const int ar = tid >> 1, ah = tid & 1;
    const __nv_bfloat16* gA = A + (size_t)(bm + ar) * lda + ah * 8;
    const int soA = ar * 8 + ah * 4;
    const int r0 = tid >> 2, kc = (tid & 3) << 2, r1 = r0 + 64;
    const float* gB0 = B + (size_t)(bn + r0) * ldb + kc;
    const float* gB1 = B + (size_t)(bn + r1) * ldb + kc;
    const int soB0 = 1024 + r0 * 16 + kc;
    const int soB1 = 1024 + r1 * 16 + kc;

    float acc[4][4][4];
#pragma unroll
    for (int i = 0; i < 4; i++)
#pragma unroll
        for (int j = 0; j < 4; j++)
#pragma unroll
            for (int r = 0; r < 4; r++) acc[i][j][r] = 0.f;

    const int nk = K >> 4;

    auto issue = [&](int t) {
        float* base = sm + (t % 3) * SF;
        cp16(base + soA,  gA + (size_t)t * 16);
        cp16(base + soB0, gB0 + (size_t)t * 16);
        cp16(base + soB1, gB1 + (size_t)t * 16);
    };

    issue(0); CP_COMMIT();
    if (nk > 1) issue(1);
    CP_COMMIT();

    for (int t = 0; t < nk; t++) {
        if (t + 2 < nk) issue(t + 2);
        CP_COMMIT();
        CP_WAIT2();
        __syncthreads();

        const unsigned* Au = (const unsigned*)(sm + (t % 3) * SF);
        const float* Bs = sm + (t % 3) * SF + 1024;

        float4 bf[4];
#pragma unroll
        for (int nt = 0; nt < 4; nt++)
            bf[nt] = *(const float4*)(Bs + (nw * 32 + nt * 8 + g) * 16 + 4 * tg);

#pragma unroll
        for (int mt = 0; mt < 4; mt++) {
            const int m0 = mw * 64 + mt * 16;
            uint2 wa0 = *(const uint2*)(Au + (m0 + g) * 8 + 2 * tg);
            uint2 wa1 = *(const uint2*)(Au + (m0 + g + 8) * 8 + 2 * tg);
            unsigned af0[4] = {wa0.x << 16, wa1.x << 16,
                               wa0.x & 0xFFFF0000u, wa1.x & 0xFFFF0000u};
            unsigned af1[4] = {wa0.y << 16, wa1.y << 16,
                               wa0.y & 0xFFFF0000u, wa1.y & 0xFFFF0000u};
#pragma unroll
            for (int nt = 0; nt < 4; nt++) {
                unsigned b0[2] = {__float_as_uint(bf[nt].x), __float_as_uint(bf[nt].y)};
                mma_tf32(acc[mt][nt], af0, b0);
            }
#pragma unroll
            for (int nt = 0; nt < 4; nt++) {
                unsigned b1[2] = {__float_as_uint(bf[nt].z), __float_as_uint(bf[nt].w)};
                mma_tf32(acc[mt][nt], af1, b1);
            }
        }
        __syncthreads();
    }

    epilogue<BIASM, RELU, ROUND>(acc, C, bias, bm, bn, ldc, mw, nw, g, tg);
}

// ========== kk_bf_body: A [k][m] BF16, B [k][n] fp32, 2-stage cp.async ==========
template<bool ROUND>
__device__ __forceinline__ void kk_bf_body(const __nv_bfloat16* __restrict__ A,
                                           const float* __restrict__ B, float* __restrict__ C,
                                           int K, int lda, int ldb, int ldc,
                                           int bm, int bn, float* sm)
{
    const int tid  = threadIdx.x;
    const int lane = tid & 31, warp = tid >> 5;
    const int mw = warp & 1, nw = warp >> 1;
    const int g = lane >> 2, tg = lane & 3;

    const int SF = 1152 + 2176;

    const int akr = tid >> 4;
    const int ac16 = tid & 15;
    const __nv_bfloat16* gA = A + (size_t)akr * lda + bm + ac16 * 8;
    const int soA = akr * 72 + ac16 * 4;
    const int kr0 = tid >> 5, kr1 = kr0 + 8, cc = (tid & 31) << 2;
    const float* gB0 = B + (size_t)kr0 * ldb + bn + cc;
    const float* gB1 = B + (size_t)kr1 * ldb + bn + cc;
    const int soB0 = 1152 + kr0 * 136 + cc;
    const int soB1 = 1152 + kr1 * 136 + cc;

    float acc[4][4][4];
#pragma unroll
    for (int i = 0; i < 4; i++)
#pragma unroll
        for (int j = 0; j < 4; j++)
#pragma unroll
            for (int r = 0; r < 4; r++) acc[i][j][r] = 0.f;

    const int nk = K >> 4;

    auto issue = [&](int t) {
        float* base = sm + (t & 1) * SF;
        const size_t ko = (size_t)t * 16;
        cp16(base + soA,  gA + ko * lda);
        cp16(base + soB0, gB0 + ko * ldb);
        cp16(base + soB1, gB1 + ko * ldb);
    };

    issue(0); CP_COMMIT();

    for (int t = 0; t < nk; t++) {
        if (t + 1 < nk) issue(t + 1);
        CP_COMMIT();
        CP_WAIT1();
        __syncthreads();

        const unsigned* Au = (const unsigned*)(sm + (t & 1) * SF);
        const float* Bs = sm + (t & 1) * SF + 1152;

#pragma unroll
        for (int ks = 0; ks < 16; ks += 8) {
            unsigned bfr[4][2];
#pragma unroll
            for (int nt = 0; nt < 4; nt++) {
                int n = nw * 32 + nt * 8 + g;
                bfr[nt][0] = __float_as_uint(Bs[(ks + tg) * 136 + n]);
                bfr[nt][1] = __float_as_uint(Bs[(ks + tg + 4) * 136 + n]);
            }
#pragma unroll
            for (int mt = 0; mt < 4; mt++) {
                int m0 = mw * 64 + mt * 16;
                int wof = (m0 >> 1) + (g >> 1);
                bool hi = (g & 1);
                unsigned w00 = Au[(ks + tg) * 72 + wof];
                unsigned w08 = Au[(ks + tg) * 72 + wof + 4];
                unsigned w40 = Au[(ks + tg + 4) * 72 + wof];
                unsigned w48 = Au[(ks + tg + 4) * 72 + wof + 4];
                unsigned af[4];
                af[0] = hi ? (w00 & 0xFFFF0000u) : (w00 << 16);
                af[1] = hi ? (w08 & 0xFFFF0000u) : (w08 << 16);
                af[2] = hi ? (w40 & 0xFFFF0000u) : (w40 << 16);
                af[3] = hi ? (w48 & 0xFFFF0000u) : (w48 << 16);
#pragma unroll
                for (int nt = 0; nt < 4; nt++)
                    mma_tf32(acc[mt][nt], af, bfr[nt]);
            }
        }
        __syncthreads();
    }

    epilogue<0, false, ROUND>(acc, C, nullptr, bm, bn, ldc, mw, nw, g, tg);
}

// ================= energy kernel (unchanged from R16) =================
__global__ __launch_bounds__(256, 2)
void gemm_energy(const float* __restrict__ l12g, const float* __restrict__ p1g,
                 const float* __restrict__ inter,
                 __nv_bfloat16* __restrict__ att, float* __restrict__ epart)
{
    extern __shared__ float sm[];
    const int nx = blockIdx.x, my = blockIdx.y, z = blockIdx.z;
    const int zb = z >> 3, zh = z & 7;
    const float* A  = l12g + (size_t)zb * (LL_ * 2 * HD_) + zh * 128;
    const float* B  = p1g  + (size_t)zb * (LP_ * HD_) + zh * 128;
    __nv_bfloat16* C = att + (size_t)zb * ((size_t)H_ * LL_ * LP_) + (size_t)zh * (LL_ * LP_);
    const float* ipt = inter + (size_t)zb * (LL_ * LP_);

    const int lda = 2048, ldb = 1024, ldc = 1024;
    const int bm = my * 128, bn = nx * 128;

    const int tid  = threadIdx.x;
    const int lane = tid & 31, warp = tid >> 5;
    const int mw = warp & 1, nw = warp >> 1;
    const int g = lane >> 2, tg = lane & 3;

    const int r0 = tid >> 2,  kc = (tid & 3) << 2;
    const int r1 = r0 + 64;
    const float* gA0 = A + (size_t)(bm + r0) * lda + kc;
    const float* gA1 = A + (size_t)(bm + r1) * lda + kc;
    const float* gB0 = B + (size_t)(bn + r0) * ldb + kc;
    const float* gB1 = B + (size_t)(bn + r1) * ldb + kc;
    const int so = r0 * 16 + kc;
    const int s1 = r1 * 16 + kc;

    float acc[4][4][4];
#pragma unroll
    for (int i = 0; i < 4; i++)
#pragma unroll
        for (int j = 0; j < 4; j++)
#pragma unroll
            for (int r = 0; r < 4; r++) acc[i][j][r] = 0.f;

    const int nk = 8;

    auto issue = [&](int t) {
        float* base = sm + (t % 3) * 4096;
        const size_t ko = (size_t)t << 4;
        cp16(base + so,        gA0 + ko);
        cp16(base + s1,        gA1 + ko);
        cp16(base + 2048 + so, gB0 + ko);
        cp16(base + 2048 + s1, gB1 + ko);
    };

    issue(0); CP_COMMIT();
    issue(1); CP_COMMIT();

    for (int t = 0; t < nk; t++) {
        if (t + 2 < nk) issue(t + 2);
        CP_COMMIT();
        CP_WAIT2();
        __syncthreads();

        const float* As = sm + (t % 3) * 4096;
        const float* Bs = As + 2048;

        float4 bf[4];
#pragma unroll
        for (int nt = 0; nt < 4; nt++)
            bf[nt] = *(const float4*)(Bs + (nw * 32 + nt * 8 + g) * 16 + 4 * tg);

#pragma unroll
        for (int mt = 0; mt < 4; mt++) {
            const int m0 = mw * 64 + mt * 16;
            float4 a0 = *(const float4*)(As + (m0 + g) * 16 + 4 * tg);
            float4 a1 = *(const float4*)(As + (m0 + g + 8) * 16 + 4 * tg);
            unsigned af0[4] = {__float_as_uint(a0.x), __float_as_uint(a1.x),
                               __float_as_uint(a0.y), __float_as_uint(a1.y)};
            unsigned af1[4] = {__float_as_uint(a0.z), __float_as_uint(a1.z),
                               __float_as_uint(a0.w), __float_as_uint(a1.w)};
#pragma unroll
            for (int nt = 0; nt < 4; nt++) {
                unsigned b0[2] = {__float_as_uint(bf[nt].x), __float_as_uint(bf[nt].y)};
                mma_tf32(acc[mt][nt], af0, b0);
            }
#pragma unroll
            for (int nt = 0; nt < 4; nt++) {
                unsigned b1[2] = {__float_as_uint(bf[nt].z), __float_as_uint(bf[nt].w)};
                mma_tf32(acc[mt][nt], af1, b1);
            }
        }
        __syncthreads();
    }

    const float inv = 0.08838834764831845f;
    float rsum[4][2];
#pragma unroll
    for (int mt = 0; mt < 4; mt++) { rsum[mt][0] = 0.f; rsum[mt][1] = 0.f; }

#pragma unroll
    for (int mt = 0; mt < 4; mt++) {
#pragma unroll
        for (int nt = 0; nt < 4; nt++) {
            int row = bm + mw * 64 + mt * 16 + g;
            int col = bn + nw * 32 + nt * 8 + 2 * tg;
            float2 ia = *(const float2*)(ipt + (size_t)row * LP_ + col);
            float2 ib = *(const float2*)(ipt + (size_t)(row + 8) * LP_ + col);
            __nv_bfloat162 p01, p23;
            p01.x = __float2bfloat16_rn(__expf(acc[mt][nt][0] * inv * ia.x));
            p01.y = __float2bfloat16_rn(__expf(acc[mt][nt][1] * inv * ia.y));
            p23.x = __float2bfloat16_rn(__expf(acc[mt][nt][2] * inv * ib.x));
            p23.y = __float2bfloat16_rn(__expf(acc[mt][nt][3] * inv * ib.y));
            *(__nv_bfloat162*)(C + (size_t)row * ldc + col) = p01;
            *(__nv_bfloat162*)(C + (size_t)(row + 8) * ldc + col) = p23;
            rsum[mt][0] += __bfloat162float(p01.x) + __bfloat162float(p01.y);
            rsum[mt][1] += __bfloat162float(p23.x) + __bfloat162float(p23.y);
        }
    }

#pragma unroll
    for (int mt = 0; mt < 4; mt++) {
#pragma unroll
        for (int r = 0; r < 2; r++) {
            float v = rsum[mt][r];
            v += __shfl_xor_sync(0xffffffffu, v, 1);
            v += __shfl_xor_sync(0xffffffffu, v, 2);
            if (tg == 0)
                sm[nw * 128 + mw * 64 + mt * 16 + g + r * 8] = v;
        }
    }
    __syncthreads();
    if (tid < 128) {
        float s = sm[tid] + sm[128 + tid] + sm[256 + tid] + sm[384 + tid];
        epart[((size_t)z * 256 + bm + tid) * 8 + nx] = s;
    }
}

__global__ void reduce_rs(const float* __restrict__ epart, float* __restrict__ rs)
{
    int i = blockIdx.x * 256 + threadIdx.x;
    const float* p = epart + (size_t)i * 8;
    float s = p[0] + p[1] + p[2] + p[3] + p[4] + p[5] + p[6] + p[7];
    rs[i] = 1.0f / s;
}

__global__ void scale_l2(const float4* __restrict__ l12v, const float* __restrict__ rs,
                         float4* __restrict__ l2s)
{
    int i = blockIdx.x * 256 + threadIdx.x;     // 1048576 -> 4096 blocks
    int hd4 = i & 255, l = (i >> 8) & 255, b = i >> 16;
    int h = hd4 >> 5;
    float r = rs[((size_t)b * 8 + h) * 256 + l];
    float4 v = l12v[(size_t)b * (LL_ * 2 * HD_ / 4) + (size_t)l * (2 * HD_ / 4) + HD_ / 4 + hd4];
    l2s[(size_t)b * (LL_ * HD_ / 4) + (size_t)l * (HD_ / 4) + hd4] =
        make_float4(tf32f(v.x * r), tf32f(v.y * r), tf32f(v.z * r), tf32f(v.w * r));
}

// ================= global kernels =================
__global__ __launch_bounds__(256, 2)
void gemm_proj(const float* __restrict__ ligr, const float* __restrict__ protr,
               const float* __restrict__ w, const float* __restrict__ bb,
               const float* __restrict__ bp1, const float* __restrict__ bp2,
               float* __restrict__ l12, float* __restrict__ p1, float* __restrict__ p2t)
{
    extern __shared__ float sm[];
    int id = blockIdx.x;
    if (id < 512) {
        int my = id >> 4, nx = id & 15;
        cp_body<1, true, true>(ligr, w + OW_L1, bb, l12,
                               128, 128, 128, 2048, my * 128, nx * 128, sm);
    } else if (id < 1536) {
        int id2 = id - 512;
        int my = id2 >> 3, nx = id2 & 7;
        cp_body<1, true, true>(protr, w + OW_P1, bp1, p1,
                               128, 128, 128, 1024, my * 128, nx * 128, sm);
    } else {
        int id2 = id - 1536;
        int zb = id2 >> 6, rem = id2 & 63;
        int my = rem >> 3, nx = rem & 7;
        cp_body<2, true, true>(w + OW_P2, protr + (size_t)zb * LP_ * HID_, bp2,
                               p2t + (size_t)zb * HD_ * LP_,
                               128, 128, 128, 1024, my * 128, nx * 128, sm);
    }
}

// fused attention-output, bf16 att; writes into extended [.,1152] buffers
__global__ __launch_bounds__(256, 2)
void gemm_av(const __nv_bfloat16* __restrict__ att, const float* __restrict__ p2t,
             const float* __restrict__ l2s, const float* __restrict__ rs,
             float* __restrict__ lig3x, float* __restrict__ prot3x)
{
    extern __shared__ float sm[];
    int id = blockIdx.x;
    if (id < 256) {
        int z = id & 127, my = id >> 7;
        int zb = z >> 3, zh = z & 7;
        const __nv_bfloat16* A = att + (size_t)zb * ((size_t)H_ * LL_ * LP_) + (size_t)zh * (LL_ * LP_);
        const float* Bp = p2t + (size_t)zb * (HD_ * LP_) + (size_t)zh * (128 * LP_);
        float* C = lig3x + (size_t)zb * (LL_ * 1152) + zh * 128;
        const float* rsz = rs + (size_t)z * 256;
        cp_bf_body<3, false, true>(A, Bp, rsz, C, 1024, LP_, LP_, 1152, my * 128, 0, sm);
    } else {
        int id2 = id - 256;
        int z = id2 >> 3, my = id2 & 7;
        int zb = z >> 3, zh = z & 7;
        const __nv_bfloat16* A = att + (size_t)zb * ((size_t)H_ * LL_ * LP_) + (size_t)zh * (LL_ * LP_);
        const float* Bl = l2s + (size_t)zb * (LL_ * HD_) + zh * 128;
        float* C = prot3x + (size_t)zb * ((size_t)LP_ * 1152) + zh * 128;
        kk_bf_body<true>(A, Bl, C, 256, LP_, HD_, 1152, my * 128, 0, sm);
    }
}

// precompute combined out-weights Bc = [(W11@W12a)^T | W12b^T] + folded biases
// blocks 0..7: lig product tiles; 8..15: prot; 16..143: residual col copies; 144: biases
__global__ __launch_bounds__(256, 2)
void prep2(const float* __restrict__ w,
           const float* __restrict__ w11r, const float* __restrict__ w21r,
           const float* __restrict__ b11, const float* __restrict__ b12,
           const float* __restrict__ b21, const float* __restrict__ b22,
           float* __restrict__ bcl, float* __restrict__ bcp, float* __restrict__ bias2)
{
    extern __shared__ float sm[];
    int id = blockIdx.x;
    if (id < 8) {
        // bcl[n][k] = sum_j W12t[n][j] * W11[k][j]  (n=0..127, k tile id*128)
        cp_body<0, false, true>(w + OW_12, w11r, nullptr, bcl,
                                128, 256, 128, 1152, 0, id * 128, sm);
    } else if (id < 16) {
        cp_body<0, false, true>(w + OW_22, w21r, nullptr, bcp,
                                128, 256, 128, 1152, 0, (id - 8) * 128, sm);
    } else if (id < 144) {
        int t = (id - 16) * 256 + threadIdx.x;   // 0..32767
        int which = t >> 14;
        int e = t & 16383;
        int n = e >> 7, c = e & 127;
        if (which == 0)
            bcl[n * 1152 + 1024 + c] = w[OW_12 + n * 256 + 128 + c];
        else
            bcp[n * 1152 + 1024 + c] = w[OW_22 + n * 256 + 128 + c];
    } else {
        int t = threadIdx.x;
        if (t < 128) {
            float s = b12[t];
            for (int j = 0; j < 128; j++) s += b11[j] * w[OW_12 + t * 256 + j];
            bias2[t] = s;
        } else {
            int n = t - 128;
            float s = b22[n];
            for (int j = 0; j < 128; j++) s += b21[j] * w[OW_22 + n * 256 + j];
            bias2[128 + n] = s;
        }
    }
}

// fused branch outputs: out = relu(A[.,1152] @ Bc^T + bias2)
__global__ __launch_bounds__(256, 2)
void gemm_out(const float* __restrict__ lig3x, const float* __restrict__ prot3x,
              const float* __restrict__ bcl, const float* __restrict__ bcp,
              const float* __restrict__ bias2,
              float* __restrict__ out_lig, float* __restrict__ out_prot)
{
    extern __shared__ float sm[];
    int id = blockIdx.x;
    if (id < 32)
        cp_body<1, true, false>(lig3x, bcl, bias2, out_lig,
                                1152, 1152, 1152, 128, id * 128, 0, sm);
    else
        cp_body<1, true, false>(prot3x, bcp, bias2 + 128, out_prot,
                                1152, 1152, 1152, 128, (id - 32) * 128, 0, sm);
}

// ---------------- merged preprocessing ----------------
// items: lig 131072 f4 | prot 524288 f4 | bias 2048 | W11 32768 f4 | W21 32768 f4
// total 722944 threads -> 2824 blocks of 256
__global__ void preproc(const float4* __restrict__ lig, const float4* __restrict__ prot,
                        const float* __restrict__ bl1, const float* __restrict__ bl2,
                        const float4* __restrict__ W11, const float4* __restrict__ W21,
                        float4* __restrict__ ligr, float4* __restrict__ protr,
                        float4* __restrict__ lig3x, float4* __restrict__ prot3x,
                        float* __restrict__ bb,
                        float4* __restrict__ w11r, float4* __restrict__ w21r)
{
    int i = blockIdx.x * 256 + threadIdx.x;
    const int n1 = B_ * LL_ * HID_ / 4;   // 131072
    const int n2 = B_ * LP_ * HID_ / 4;   // 524288
    if (i < n1) {
        float4 v = lig[i];
        v = make_float4(tf32f(v.x), tf32f(v.y), tf32f(v.z), tf32f(v.w));
        ligr[i] = v;
        int r = i >> 5, c = i & 31;
        lig3x[(size_t)r * 288 + 256 + c] = v;
    } else if (i < n1 + n2) {
        int j = i - n1;
        float4 v = prot[j];
        v = make_float4(tf32f(v.x), tf32f(v.y), tf32f(v.z), tf32f(v.w));
        protr[j] = v;
        int r = j >> 5, c = j & 31;
        prot3x[(size_t)r * 288 + 256 + c] = v;
    } else if (i < n1 + n2 + 2048) {
        int j = i - n1 - n2;
        if (j < 1024) bb[j] = bl1[j];
        else bb[j] = bl2[j - 1024];
    } else if (i < n1 + n2 + 2048 + 32768) {
        int j = i - n1 - n2 - 2048;
        float4 v = W11[j];
        w11r[j] = make_float4(tf32f(v.x), tf32f(v.y), tf32f(v.z), tf32f(v.w));
    } else {
        int j = i - n1 - n2 - 2048 - 32768;
        float4 v = W21[j];
        w21r[j] = make_float4(tf32f(v.x), tf32f(v.y), tf32f(v.z), tf32f(v.w));
    }
}

__global__ void transpose_round8(const float* w0, const float* w1, const float* w2,
                                 const float* w3, const float* w4, const float* w5,
                                 const float* w6, const float* w7, float* wb)
{
    const float* ins[8] = {w0, w1, w2, w3, w4, w5, w6, w7};
    const int Rs[8]   = {128, 128, 128, 128, 1024, 1024, 256, 256};
    const int Cs[8]   = {1024, 1024, 1024, 1024, 128, 128, 128, 128};
    const int offs[8] = {OW_L1, OW_L2, OW_P1, OW_P2, OW_11, OW_21, OW_12, OW_22};
    int zi = blockIdx.z;
    int R = Rs[zi], C = Cs[zi];
    int bx = blockIdx.x * 32, by = blockIdx.y * 32;
    if (bx >= C || by >= R) return;
    const float* in = ins[zi];
    float* out = wb + offs[zi];

    __shared__ float t[32][33];
    int tx = threadIdx.x, ty = threadIdx.y;
#pragma unroll
    for (int j = 0; j < 32; j += 8)
        t[ty + j][tx] = in[(size_t)(by + ty + j) * C + bx + tx];
    __syncthreads();
#pragma unroll
    for (int j = 0; j < 32; j += 8)
        out[(size_t)(bx + ty + j) * R + by + tx] = tf32f(t[tx][ty + j]);
}

// ---------------- launcher ----------------
extern "C" void kernel_launch(void* const* d_in, const int* in_sizes, int n_in,
                              void* d_out, int out_size)
{
    const float* ligand = (const float*)d_in[0];
    const float* prot   = (const float*)d_in[1];
    const float* inter  = (const float*)d_in[2];
    const float* Wl1 = (const float*)d_in[3];  const float* bl1 = (const float*)d_in[4];
    const float* Wl2 = (const float*)d_in[5];  const float* bl2 = (const float*)d_in[6];
    const float* Wp1 = (const float*)d_in[7];  const float* bp1 = (const float*)d_in[8];
    const float* Wp2 = (const float*)d_in[9];  const float* bp2 = (const float*)d_in[10];
    const float* W11 = (const float*)d_in[11]; const float* b11 = (const float*)d_in[12];
    const float* W12 = (const float*)d_in[13]; const float* b12 = (const float*)d_in[14];
    const float* W21 = (const float*)d_in[15]; const float* b21 = (const float*)d_in[16];
    const float* W22 = (const float*)d_in[17]; const float* b22 = (const float*)d_in[18];

    float* out_lig  = (float*)d_out;
    float* out_prot = out_lig + (size_t)B_ * LL_ * HID_;

    float *l12, *p1, *p2t, *lig3x, *prot3x, *ligr, *protr, *w, *bb;
    float *l2s, *epart, *rs, *w11r, *w21r, *bcl, *bcp, *bias2;
    __nv_bfloat16* att;
    cudaGetSymbolAddress((void**)&l12, g_l12);
    cudaGetSymbolAddress((void**)&p1, g_p1);
    cudaGetSymbolAddress((void**)&p2t, g_p2t);
    cudaGetSymbolAddress((void**)&att, g_att);
    cudaGetSymbolAddress((void**)&lig3x, g_lig3x);
    cudaGetSymbolAddress((void**)&prot3x, g_prot3x);
    cudaGetSymbolAddress((void**)&ligr, g_ligr);
    cudaGetSymbolAddress((void**)&protr, g_protr);
    cudaGetSymbolAddress((void**)&w, g_w);
    cudaGetSymbolAddress((void**)&bb, g_b12);
    cudaGetSymbolAddress((void**)&l2s, g_l2s);
    cudaGetSymbolAddress((void**)&epart, g_epart);
    cudaGetSymbolAddress((void**)&rs, g_rs);
    cudaGetSymbolAddress((void**)&w11r, g_w11r);
    cudaGetSymbolAddress((void**)&w21r, g_w21r);
    cudaGetSymbolAddress((void**)&bcl, g_bcl);
    cudaGetSymbolAddress((void**)&bcp, g_bcp);
    cudaGetSymbolAddress((void**)&bias2, g_bias2);

    dim3 blk(256);
    const int SMEM = 49152;

    // --- preprocessing: 131072+524288+2048+32768+32768 = 722944 -> 2824 blocks ---
    preproc<<<2824, 256>>>((const float4*)ligand, (const float4*)prot, bl1, bl2,
                           (const float4*)W11, (const float4*)W21,
                           (float4*)ligr, (float4*)protr,
                           (float4*)lig3x, (float4*)prot3x, bb,
                           (float4*)w11r, (float4*)w21r);
    transpose_round8<<<dim3(32, 32, 8), dim3(32, 8)>>>(
        Wl1, Wl2, Wp1, Wp2, W11, W21, W12, W22, w);

    // --- combined out-weight precompute (16 GEMM tiles + 128 copy + 1 bias = 145) ---
    prep2<<<145, blk, SMEM>>>(w, w11r, w21r, b11, b12, b21, b22, bcl, bcp, bias2);

    // --- all three projections (2560 CTAs) ---
    gemm_proj<<<2560, blk, SMEM>>>(ligr, protr, w, bb, bp1, bp2, l12, p1, p2t);

    // --- energy with fused exp/gating epilogue (bf16 att) + partial row sums ---
    gemm_energy<<<dim3(8, 2, 128), blk, SMEM>>>(l12, p1, inter, att, epart);

    // --- reciprocal row sums + scaled l2 ---
    reduce_rs<<<128, 256>>>(epart, rs);
    scale_l2<<<4096, 256>>>((const float4*)l12, rs, (float4*)l2s);

    // --- fused lig3 + prot3 into extended buffers (1280 CTAs, long first) ---
    gemm_av<<<1280, blk, SMEM>>>(att, p2t, l2s, rs, lig3x, prot3x);

    // --- single fused branch-output GEMM (32 + 128 = 160 CTAs, K=1152) ---
    gemm_out<<<160, blk, SMEM>>>(lig3x, prot3x, bcl, bcp, bias2, out_lig, out_prot);
}